// round 15
// baseline (speedup 1.0000x reference)
#include <cuda_runtime.h>
#include <cstdint>
#include <cstddef>

#define NUM_USERS 10000
#define EMBED_DIM 64
#define BATCH     4096
#define TM        128            // b rows per CTA
#define CK        32             // u per chunk (K per stage)
#define SPLITS    9
#define NCH       313            // ceil(10000/32)
#define NTILES    (BATCH / TM)   // 32
#define STAGES    4

// smem stage: A = raw fp32 W tile [128][36f pitch]; B = fragment-major tf32 (8KB)
#define A_PITCH_B 144            // 36 floats/row: bank = 4r+c -> conflict-free A frags
#define OFF_A     0
#define A_BYTES   (TM * A_PITCH_B)        // 18432
#define OFF_B     A_BYTES
#define B_BYTES   8192                    // 4ks x 4q x 32lanes x 16B
#define STAGE_STRIDE (A_BYTES + B_BYTES)  // 26624
#define DSM_SIZE  (STAGES * STAGE_STRIDE) // 106496

// Precomputed E in tf32, FRAGMENT-MAJOR: [chunk][ks][q][lane] -> 16B
//   lane: tig=lane&3, g=lane>>2;  k0=ks*8+tig;  n0=(2q)*8+g; n1=n0+8
//   words = { B(k0,n0), B(k0+4,n0), B(k0,n1), B(k0+4,n1) },  B(k,n)=E[u0+k][n]
__device__ __align__(16) uint32_t g_Bf[NCH * 512 * 4];
__device__ float        g_partials[SPLITS][BATCH];
__device__ unsigned int g_cnt[NTILES];

// ---------------- helpers ----------------
__device__ __forceinline__ uint32_t smem_u32(const void* p) {
    uint32_t a;
    asm("{ .reg .u64 t; cvta.to.shared.u64 t, %1; cvt.u32.u64 %0, t; }" : "=r"(a) : "l"(p));
    return a;
}
__device__ __forceinline__ uint32_t f2tf(float f) {
    uint32_t r;
    asm("cvt.rna.tf32.f32 %0, %1;" : "=r"(r) : "f"(f));
    return r;
}
__device__ __forceinline__ void lds_f32(float& d, uint32_t a) {
    asm volatile("ld.shared.f32 %0, [%1];" : "=f"(d) : "r"(a));
}
__device__ __forceinline__ void lds128(uint4& v, uint32_t a) {
    asm volatile("ld.shared.v4.b32 {%0,%1,%2,%3}, [%4];"
        : "=r"(v.x), "=r"(v.y), "=r"(v.z), "=r"(v.w) : "r"(a));
}
__device__ __forceinline__ void cp_async16(uint32_t dst, const void* src) {
    asm volatile("{ .reg .u64 g; cvta.to.global.u64 g, %1; cp.async.cg.shared.global [%0], [g], 16; }"
        :: "r"(dst), "l"(src));
}
__device__ __forceinline__ void cp_async16z(uint32_t dst, const void* src, uint32_t sz) {
    asm volatile("{ .reg .u64 g; cvta.to.global.u64 g, %1; cp.async.cg.shared.global [%0], [g], 16, %2; }"
        :: "r"(dst), "l"(src), "r"(sz));
}
#define CP_COMMIT() asm volatile("cp.async.commit_group;" ::: "memory")
#define CP_WAIT2()  asm volatile("cp.async.wait_group 2;" ::: "memory")

__device__ __forceinline__ void mma_tf32(float4& c, const uint32_t* a, uint32_t b0, uint32_t b1) {
    asm volatile(
        "mma.sync.aligned.m16n8k8.row.col.f32.tf32.tf32.f32 "
        "{%0,%1,%2,%3}, {%4,%5,%6,%7}, {%8,%9}, {%0,%1,%2,%3};"
        : "+f"(c.x), "+f"(c.y), "+f"(c.z), "+f"(c.w)
        : "r"(a[0]), "r"(a[1]), "r"(a[2]), "r"(a[3]), "r"(b0), "r"(b1));
}

// Index dtype sniff: int64 iff all sampled high words are zero.
__device__ __forceinline__ int sniff_is64(const void* items_raw, int tid) {
    const unsigned int* iw = (const unsigned int*)items_raw;
    int any = (tid < 256) ? (iw[2 * tid + 1] != 0u) : 0;
    return __syncthreads_or(any) == 0;
}
__device__ __forceinline__ int load_idx(const void* raw, int i, int is64) {
    return is64 ? (int)((const long long*)raw)[i] : ((const int*)raw)[i];
}

// ---------------- setup: E -> tf32 fragment-major image (CK=32 chunks) ----------------
__global__ void setup_b_kernel(const float* __restrict__ user_emb) {
    __shared__ float sE[32 * 65];
    const int c = blockIdx.x;           // chunk 0..312
    const int t = threadIdx.x;

    #pragma unroll
    for (int i = 0; i < 2; i++) {
        int idx = t + i * 256;          // 0..511
        int row = idx >> 4;             // u local (k) 0..31
        int q4  = idx & 15;
        int u   = c * CK + row;
        float4 v = (u < NUM_USERS) ? *(const float4*)&user_emb[(size_t)u * EMBED_DIM + q4 * 4]
                                   : make_float4(0.f, 0.f, 0.f, 0.f);
        sE[row * 65 + q4 * 4 + 0] = v.x;
        sE[row * 65 + q4 * 4 + 1] = v.y;
        sE[row * 65 + q4 * 4 + 2] = v.z;
        sE[row * 65 + q4 * 4 + 3] = v.w;
    }
    __syncthreads();
    #pragma unroll
    for (int i = 0; i < 2; i++) {
        int idx  = t + i * 256;         // (ks,q,lane) linear, 0..511
        int lane = idx & 31;
        int q    = (idx >> 5) & 3;
        int ks   = idx >> 7;            // 0..3
        int tig  = lane & 3, g = lane >> 2;
        int k0 = ks * 8 + tig;
        int n0 = (2 * q) * 8 + g;
        uint4 w;
        w.x = f2tf(sE[k0 * 65 + n0]);
        w.y = f2tf(sE[(k0 + 4) * 65 + n0]);
        w.z = f2tf(sE[k0 * 65 + n0 + 8]);
        w.w = f2tf(sE[(k0 + 4) * 65 + n0 + 8]);
        *(uint4*)&g_Bf[((size_t)c * 512 + idx) * 4] = w;
    }
}

// ---------------- fused kernel: 4-stage cp.async pipeline, tf32 single pass ----------------
__global__ __launch_bounds__(256, 2)
void bpr_kernel(const float* __restrict__ user_emb,
                const float* __restrict__ item_emb,
                const float* __restrict__ social,
                const void*  __restrict__ users_raw,
                const void*  __restrict__ items_raw,
                float* __restrict__ out)
{
    extern __shared__ __align__(16) char dsm[];
    __shared__ int sU[TM];
    __shared__ int sI[TM];
    __shared__ unsigned int s_old;

    const uint32_t sb  = smem_u32(dsm);
    const int tid  = threadIdx.x;
    const int wid  = tid >> 5;
    const int lane = tid & 31;
    const int b0    = blockIdx.x * TM;
    const int split = blockIdx.y;

    const int is64 = sniff_is64(items_raw, tid);
    if (tid < TM) {
        sU[tid] = load_idx(users_raw, b0 + tid, is64);
        sI[tid] = load_idx(items_raw, b0 + tid, is64);
    }
    __syncthreads();

    // ---- A staging: thread covers rows strow+32p (p=0..3), 16B segment scol8 ----
    const int strow = tid >> 3;          // 0..31
    const int scol8 = tid & 7;           // 8 x 16B = 128B row
    const float* aSrc[4];
    #pragma unroll
    for (int p = 0; p < 4; p++)
        aSrc[p] = social + (size_t)sU[strow + p * 32] * NUM_USERS + scol8 * 4;
    const uint32_t aDst0 = (uint32_t)(strow * A_PITCH_B + scol8 * 16);

    // ---- fragment geometry (per lane) ----
    const uint32_t aFragBase = (uint32_t)((wid * 16 + (lane >> 2)) * A_PITCH_B + (lane & 3) * 4);
    const uint32_t bLaneOff  = (uint32_t)(lane * 16);

    float4 acc[8];
    #pragma unroll
    for (int n = 0; n < 8; n++) acc[n] = make_float4(0.f, 0.f, 0.f, 0.f);

    const int nchunks = (NCH - split + SPLITS - 1) / SPLITS;   // >= 34 for all splits

    // ---- stage loader ----
    auto stage_load = [&](int s, int c) {
        const uint32_t bo = sb + (uint32_t)(s * STAGE_STRIDE);
        const int u0 = c * CK;
        const uint32_t sz = (u0 + scol8 * 4 < NUM_USERS) ? 16u : 0u;  // 10000 % 4 == 0
        #pragma unroll
        for (int p = 0; p < 4; p++)
            cp_async16z(bo + OFF_A + aDst0 + (uint32_t)(p * 32 * A_PITCH_B), aSrc[p] + u0, sz);
        #pragma unroll
        for (int p = 0; p < 2; p++) {
            uint32_t idx = (uint32_t)(tid + p * 256);
            cp_async16(bo + OFF_B + idx * 16, g_Bf + ((size_t)c * 512 + idx) * 4);
        }
    };

    // ---- prologue: fill stages 0..2 ----
    #pragma unroll
    for (int i = 0; i < 3; i++) {
        stage_load(i, split + i * SPLITS);
        CP_COMMIT();
    }

    // ---- mainloop ----
    for (int i = 0; i < nchunks; i++) {
        CP_WAIT2();                     // stage i&3 (chunk i) has landed
        __syncthreads();                // all warps done with stage (i-1)&3; data published

        // issue chunk i+3 into stage (i+3)&3 == (i-1)&3
        const int cn = split + (i + 3) * SPLITS;
        if (cn < NCH) stage_load((i + 3) & 3, cn);
        CP_COMMIT();                    // always commit to keep group counting uniform

        // compute stage i&3: per ks = 4 scalar LDS + 4 cvt + 4 LDS.128 + 8 MMA
        {
            const uint32_t bo = sb + (uint32_t)((i & 3) * STAGE_STRIDE);
            const uint32_t aB = bo + OFF_A + aFragBase;
            const uint32_t bB = bo + OFF_B + bLaneOff;
            #pragma unroll
            for (int ks = 0; ks < 4; ks++) {
                float f0, f1, f2, f3;
                const uint32_t ka = aB + (uint32_t)(ks * 32);
                lds_f32(f0, ka);
                lds_f32(f1, ka + 8 * A_PITCH_B);
                lds_f32(f2, ka + 16);
                lds_f32(f3, ka + 16 + 8 * A_PITCH_B);
                uint32_t a[4] = { f2tf(f0), f2tf(f1), f2tf(f2), f2tf(f3) };
                #pragma unroll
                for (int q = 0; q < 4; q++) {
                    uint4 w;
                    lds128(w, bB + (uint32_t)((ks * 4 + q) * 512));
                    mma_tf32(acc[2 * q],     a, w.x, w.y);
                    mma_tf32(acc[2 * q + 1], a, w.z, w.w);
                }
            }
        }
    }

    // ---- epilogue: dot with bi, reduce across 4 lanes per row ----
    {
        const int r0 = wid * 16 + (lane >> 2);
        const int r1 = r0 + 8;
        const float* ip0 = item_emb + (size_t)sI[r0] * EMBED_DIM;
        const float* ip1 = item_emb + (size_t)sI[r1] * EMBED_DIM;
        const int cbase = (lane & 3) * 2;
        float v0 = 0.f, v1 = 0.f;
        #pragma unroll
        for (int n = 0; n < 8; n++) {
            const int cn = n * 8 + cbase;
            float2 e0 = *(const float2*)(ip0 + cn);
            float2 e1 = *(const float2*)(ip1 + cn);
            v0 += acc[n].x * e0.x + acc[n].y * e0.y;
            v1 += acc[n].z * e1.x + acc[n].w * e1.y;
        }
        v0 += __shfl_xor_sync(0xffffffffu, v0, 1);
        v0 += __shfl_xor_sync(0xffffffffu, v0, 2);
        v1 += __shfl_xor_sync(0xffffffffu, v1, 1);
        v1 += __shfl_xor_sync(0xffffffffu, v1, 2);
        if ((lane & 3) == 0) {
            g_partials[split][b0 + r0] = v0;
            g_partials[split][b0 + r1] = v1;
        }
    }
    __syncthreads();

    // ---- last split for this b-tile: fixed-order sum + pos term (deterministic) ----
    if (tid == 0) {
        __threadfence();
        s_old = atomicAdd(&g_cnt[blockIdx.x], 1u);
    }
    __syncthreads();
    if (s_old == SPLITS - 1) {
        __threadfence();
        if (tid < TM) {
            const int b = b0 + tid;
            float s = 0.f;
            #pragma unroll
            for (int p = 0; p < SPLITS; p++) s += g_partials[p][b];
            const float4* ue = (const float4*)(user_emb + (size_t)sU[tid] * EMBED_DIM);
            const float4* ie = (const float4*)(item_emb + (size_t)sI[tid] * EMBED_DIM);
            float d = 0.f;
            #pragma unroll
            for (int k = 0; k < 16; k++) {
                float4 a = ue[k], c2 = ie[k];
                d += a.x * c2.x + a.y * c2.y + a.z * c2.z + a.w * c2.w;
            }
            out[b] = s + d;
        }
        __syncthreads();
        if (tid == 0) g_cnt[blockIdx.x] = 0u;   // self-reset for graph replay
    }
}

extern "C" void kernel_launch(void* const* d_in, const int* in_sizes, int n_in,
                              void* d_out, int out_size)
{
    const float* user_emb = (const float*)d_in[0];   // [10000, 64]
    const float* item_emb = (const float*)d_in[1];   // [100000, 64]
    const float* social   = (const float*)d_in[2];   // [10000, 10000]
    const void*  users    = d_in[3];                 // [4096] idx
    const void*  items    = d_in[4];                 // [4096] idx

    cudaFuncSetAttribute((const void*)bpr_kernel,
                         cudaFuncAttributeMaxDynamicSharedMemorySize, DSM_SIZE);

    setup_b_kernel<<<NCH, 256>>>(user_emb);

    dim3 grid(NTILES, SPLITS);   // 32 x 9 = 288 CTAs, one wave @ occ 2
    bpr_kernel<<<grid, 256, DSM_SIZE>>>(user_emb, item_emb, social, users, items, (float*)d_out);
}

// round 16
// speedup vs baseline: 1.0919x; 1.0919x over previous
#include <cuda_runtime.h>
#include <cstdint>
#include <cstddef>

#define NUM_USERS 10000
#define EMBED_DIM 64
#define BATCH     4096
#define TM        256            // b rows per CTA (8 warps x M=32)
#define CK        32             // u per chunk (K per stage)
#define SPLITS    9
#define NCH       313            // ceil(10000/32)
#define NTILES    (BATCH / TM)   // 16
#define STAGES    3

// smem stage: A = raw fp32 W tile [256][36f pitch]; B = fragment-major tf32 (8KB)
#define A_PITCH_B 144            // 36 floats/row: bank = 4r+t -> conflict-free A frags
#define OFF_A     0
#define A_BYTES   (TM * A_PITCH_B)        // 36864
#define OFF_B     A_BYTES
#define B_BYTES   8192                    // 4ks x 4q x 32lanes x 16B
#define STAGE_STRIDE (A_BYTES + B_BYTES)  // 45056
#define DSM_SIZE  (STAGES * STAGE_STRIDE) // 135168

// Precomputed E in tf32, FRAGMENT-MAJOR: [chunk][ks][q][lane] -> 16B
//   lane: tig=lane&3, g=lane>>2;  k0=ks*8+tig;  n0=(2q)*8+g; n1=n0+8
//   words = { B(k0,n0), B(k0+4,n0), B(k0,n1), B(k0+4,n1) },  B(k,n)=E[u0+k][n]
__device__ __align__(16) uint32_t g_Bf[NCH * 512 * 4];
__device__ float        g_partials[SPLITS][BATCH];
__device__ unsigned int g_cnt[NTILES];

// ---------------- helpers ----------------
__device__ __forceinline__ uint32_t smem_u32(const void* p) {
    uint32_t a;
    asm("{ .reg .u64 t; cvta.to.shared.u64 t, %1; cvt.u32.u64 %0, t; }" : "=r"(a) : "l"(p));
    return a;
}
__device__ __forceinline__ uint32_t f2tf(float f) {
    uint32_t r;
    asm("cvt.rna.tf32.f32 %0, %1;" : "=r"(r) : "f"(f));
    return r;
}
__device__ __forceinline__ void lds_f32(float& d, uint32_t a) {
    asm volatile("ld.shared.f32 %0, [%1];" : "=f"(d) : "r"(a));
}
__device__ __forceinline__ void lds128(uint4& v, uint32_t a) {
    asm volatile("ld.shared.v4.b32 {%0,%1,%2,%3}, [%4];"
        : "=r"(v.x), "=r"(v.y), "=r"(v.z), "=r"(v.w) : "r"(a));
}
__device__ __forceinline__ void cp_async16(uint32_t dst, const void* src) {
    asm volatile("{ .reg .u64 g; cvta.to.global.u64 g, %1; cp.async.cg.shared.global [%0], [g], 16; }"
        :: "r"(dst), "l"(src));
}
__device__ __forceinline__ void cp_async16z(uint32_t dst, const void* src, uint32_t sz) {
    asm volatile("{ .reg .u64 g; cvta.to.global.u64 g, %1; cp.async.cg.shared.global [%0], [g], 16, %2; }"
        :: "r"(dst), "l"(src), "r"(sz));
}
#define CP_COMMIT() asm volatile("cp.async.commit_group;" ::: "memory")
#define CP_WAIT1()  asm volatile("cp.async.wait_group 1;" ::: "memory")

__device__ __forceinline__ void mma_tf32(float4& c, const uint32_t* a, uint32_t b0, uint32_t b1) {
    asm volatile(
        "mma.sync.aligned.m16n8k8.row.col.f32.tf32.tf32.f32 "
        "{%0,%1,%2,%3}, {%4,%5,%6,%7}, {%8,%9}, {%0,%1,%2,%3};"
        : "+f"(c.x), "+f"(c.y), "+f"(c.z), "+f"(c.w)
        : "r"(a[0]), "r"(a[1]), "r"(a[2]), "r"(a[3]), "r"(b0), "r"(b1));
}

// Index dtype sniff: int64 iff all sampled high words are zero.
__device__ __forceinline__ int sniff_is64(const void* items_raw, int tid) {
    const unsigned int* iw = (const unsigned int*)items_raw;
    int any = (tid < 256) ? (iw[2 * tid + 1] != 0u) : 0;
    return __syncthreads_or(any) == 0;
}
__device__ __forceinline__ int load_idx(const void* raw, int i, int is64) {
    return is64 ? (int)((const long long*)raw)[i] : ((const int*)raw)[i];
}

// ---------------- setup: E -> tf32 fragment-major image (CK=32 chunks) ----------------
__global__ void setup_b_kernel(const float* __restrict__ user_emb) {
    __shared__ float sE[32 * 65];
    const int c = blockIdx.x;           // chunk 0..312
    const int t = threadIdx.x;

    #pragma unroll
    for (int i = 0; i < 2; i++) {
        int idx = t + i * 256;          // 0..511
        int row = idx >> 4;             // u local (k) 0..31
        int q4  = idx & 15;
        int u   = c * CK + row;
        float4 v = (u < NUM_USERS) ? *(const float4*)&user_emb[(size_t)u * EMBED_DIM + q4 * 4]
                                   : make_float4(0.f, 0.f, 0.f, 0.f);
        sE[row * 65 + q4 * 4 + 0] = v.x;
        sE[row * 65 + q4 * 4 + 1] = v.y;
        sE[row * 65 + q4 * 4 + 2] = v.z;
        sE[row * 65 + q4 * 4 + 3] = v.w;
    }
    __syncthreads();
    #pragma unroll
    for (int i = 0; i < 2; i++) {
        int idx  = t + i * 256;         // (ks,q,lane) linear, 0..511
        int lane = idx & 31;
        int q    = (idx >> 5) & 3;
        int ks   = idx >> 7;            // 0..3
        int tig  = lane & 3, g = lane >> 2;
        int k0 = ks * 8 + tig;
        int n0 = (2 * q) * 8 + g;
        uint4 w;
        w.x = f2tf(sE[k0 * 65 + n0]);
        w.y = f2tf(sE[(k0 + 4) * 65 + n0]);
        w.z = f2tf(sE[k0 * 65 + n0 + 8]);
        w.w = f2tf(sE[(k0 + 4) * 65 + n0 + 8]);
        *(uint4*)&g_Bf[((size_t)c * 512 + idx) * 4] = w;
    }
}

// ---------------- fused kernel: M=32/warp, 3-stage pipeline, tf32 single pass ----------------
__global__ __launch_bounds__(256, 1)
void bpr_kernel(const float* __restrict__ user_emb,
                const float* __restrict__ item_emb,
                const float* __restrict__ social,
                const void*  __restrict__ users_raw,
                const void*  __restrict__ items_raw,
                float* __restrict__ out)
{
    extern __shared__ __align__(16) char dsm[];
    __shared__ int sU[TM];
    __shared__ int sI[TM];
    __shared__ unsigned int s_old;

    const uint32_t sb  = smem_u32(dsm);
    const int tid  = threadIdx.x;
    const int wid  = tid >> 5;
    const int lane = tid & 31;
    const int b0    = blockIdx.x * TM;
    const int split = blockIdx.y;

    const int is64 = sniff_is64(items_raw, tid);
    sU[tid] = load_idx(users_raw, b0 + tid, is64);
    sI[tid] = load_idx(items_raw, b0 + tid, is64);
    __syncthreads();

    // ---- A staging: thread covers rows strow+32p (p=0..7), 16B segment scol8 ----
    const int strow = tid >> 3;          // 0..31
    const int scol8 = tid & 7;           // 8 x 16B = 128B row
    const float* aSrc[8];
    #pragma unroll
    for (int p = 0; p < 8; p++)
        aSrc[p] = social + (size_t)sU[strow + p * 32] * NUM_USERS + scol8 * 4;
    const uint32_t aDst0 = (uint32_t)(strow * A_PITCH_B + scol8 * 16);

    // ---- fragment geometry (per lane) ----
    // warp owns rows wid*32..wid*32+31: m-tile0 = rows +0/+8, m-tile1 = rows +16/+24
    const uint32_t aFragBase = (uint32_t)((wid * 32 + (lane >> 2)) * A_PITCH_B + (lane & 3) * 4);
    const uint32_t bLaneOff  = (uint32_t)(lane * 16);

    float4 acc[16];
    #pragma unroll
    for (int n = 0; n < 16; n++) acc[n] = make_float4(0.f, 0.f, 0.f, 0.f);

    const int nchunks = (NCH - split + SPLITS - 1) / SPLITS;

    // ---- stage loader ----
    auto stage_load = [&](int s, int c) {
        const uint32_t bo = sb + (uint32_t)(s * STAGE_STRIDE);
        const int u0 = c * CK;
        const uint32_t sz = (u0 + scol8 * 4 < NUM_USERS) ? 16u : 0u;  // 10000 % 4 == 0
        #pragma unroll
        for (int p = 0; p < 8; p++)
            cp_async16z(bo + OFF_A + aDst0 + (uint32_t)(p * 32 * A_PITCH_B), aSrc[p] + u0, sz);
        #pragma unroll
        for (int p = 0; p < 2; p++) {
            uint32_t idx = (uint32_t)(tid + p * 256);
            cp_async16(bo + OFF_B + idx * 16, g_Bf + ((size_t)c * 512 + idx) * 4);
        }
    };

    // ---- prologue: fill stages 0,1 ----
    stage_load(0, split);
    CP_COMMIT();
    if (split + SPLITS < NCH) stage_load(1, split + SPLITS);
    CP_COMMIT();

    // ---- mainloop ----
    int s = 0;                           // stage of chunk i
    for (int i = 0; i < nchunks; i++) {
        CP_WAIT1();                     // chunk i has landed (chunk i+1 may fly)
        __syncthreads();                // all warps done computing chunk i-1

        // issue chunk i+2 into stage (s+2)%3
        const int cn = split + (i + 2) * SPLITS;
        int sl = s + 2; if (sl >= 3) sl -= 3;
        if (cn < NCH) stage_load(sl, cn);
        CP_COMMIT();                    // uniform group counting

        // compute stage s: per ks = 8 scalar LDS + 8 cvt + 4 LDS.128 + 16 MMA
        {
            const uint32_t bo = sb + (uint32_t)(s * STAGE_STRIDE);
            const uint32_t aB = bo + OFF_A + aFragBase;
            const uint32_t bB = bo + OFF_B + bLaneOff;
            #pragma unroll
            for (int ks = 0; ks < 4; ks++) {
                const uint32_t ka = aB + (uint32_t)(ks * 32);
                float f0, f1, f2, f3, g0, g1, g2, g3;
                lds_f32(f0, ka);
                lds_f32(f1, ka + 8 * A_PITCH_B);
                lds_f32(f2, ka + 16);
                lds_f32(f3, ka + 16 + 8 * A_PITCH_B);
                lds_f32(g0, ka + 16 * A_PITCH_B);
                lds_f32(g1, ka + 24 * A_PITCH_B);
                lds_f32(g2, ka + 16 + 16 * A_PITCH_B);
                lds_f32(g3, ka + 16 + 24 * A_PITCH_B);
                uint32_t a0[4] = { f2tf(f0), f2tf(f1), f2tf(f2), f2tf(f3) };
                uint32_t a1[4] = { f2tf(g0), f2tf(g1), f2tf(g2), f2tf(g3) };
                #pragma unroll
                for (int q = 0; q < 4; q++) {
                    uint4 w;
                    lds128(w, bB + (uint32_t)((ks * 4 + q) * 512));
                    mma_tf32(acc[2 * q],          a0, w.x, w.y);
                    mma_tf32(acc[2 * q + 1],      a0, w.z, w.w);
                    mma_tf32(acc[8 + 2 * q],      a1, w.x, w.y);
                    mma_tf32(acc[8 + 2 * q + 1],  a1, w.z, w.w);
                }
            }
        }
        if (++s == 3) s = 0;
    }

    // ---- epilogue: dot with bi, reduce across 4 lanes per row ----
    {
        const int rb = wid * 32 + (lane >> 2);
        const int cbase = (lane & 3) * 2;
        float v[4] = {0.f, 0.f, 0.f, 0.f};
        const float* ip[4];
        ip[0] = item_emb + (size_t)sI[rb]      * EMBED_DIM;
        ip[1] = item_emb + (size_t)sI[rb + 8]  * EMBED_DIM;
        ip[2] = item_emb + (size_t)sI[rb + 16] * EMBED_DIM;
        ip[3] = item_emb + (size_t)sI[rb + 24] * EMBED_DIM;
        #pragma unroll
        for (int n = 0; n < 8; n++) {
            const int cn = n * 8 + cbase;
            float2 e0 = *(const float2*)(ip[0] + cn);
            float2 e1 = *(const float2*)(ip[1] + cn);
            float2 e2 = *(const float2*)(ip[2] + cn);
            float2 e3 = *(const float2*)(ip[3] + cn);
            v[0] += acc[n].x     * e0.x + acc[n].y     * e0.y;
            v[1] += acc[n].z     * e1.x + acc[n].w     * e1.y;
            v[2] += acc[8 + n].x * e2.x + acc[8 + n].y * e2.y;
            v[3] += acc[8 + n].z * e3.x + acc[8 + n].w * e3.y;
        }
        #pragma unroll
        for (int k = 0; k < 4; k++) {
            v[k] += __shfl_xor_sync(0xffffffffu, v[k], 1);
            v[k] += __shfl_xor_sync(0xffffffffu, v[k], 2);
        }
        if ((lane & 3) == 0) {
            g_partials[split][b0 + rb]      = v[0];
            g_partials[split][b0 + rb + 8]  = v[1];
            g_partials[split][b0 + rb + 16] = v[2];
            g_partials[split][b0 + rb + 24] = v[3];
        }
    }
    __syncthreads();

    // ---- last split for this b-tile: fixed-order sum + pos term (deterministic) ----
    if (tid == 0) {
        __threadfence();
        s_old = atomicAdd(&g_cnt[blockIdx.x], 1u);
    }
    __syncthreads();
    if (s_old == SPLITS - 1) {
        __threadfence();
        {
            const int b = b0 + tid;
            float s2 = 0.f;
            #pragma unroll
            for (int p = 0; p < SPLITS; p++) s2 += g_partials[p][b];
            const float4* ue = (const float4*)(user_emb + (size_t)sU[tid] * EMBED_DIM);
            const float4* ie = (const float4*)(item_emb + (size_t)sI[tid] * EMBED_DIM);
            float d = 0.f;
            #pragma unroll
            for (int k = 0; k < 16; k++) {
                float4 a = ue[k], c2 = ie[k];
                d += a.x * c2.x + a.y * c2.y + a.z * c2.z + a.w * c2.w;
            }
            out[b] = s2 + d;
        }
        __syncthreads();
        if (tid == 0) g_cnt[blockIdx.x] = 0u;   // self-reset for graph replay
    }
}

extern "C" void kernel_launch(void* const* d_in, const int* in_sizes, int n_in,
                              void* d_out, int out_size)
{
    const float* user_emb = (const float*)d_in[0];   // [10000, 64]
    const float* item_emb = (const float*)d_in[1];   // [100000, 64]
    const float* social   = (const float*)d_in[2];   // [10000, 10000]
    const void*  users    = d_in[3];                 // [4096] idx
    const void*  items    = d_in[4];                 // [4096] idx

    cudaFuncSetAttribute((const void*)bpr_kernel,
                         cudaFuncAttributeMaxDynamicSharedMemorySize, DSM_SIZE);

    setup_b_kernel<<<NCH, 256>>>(user_emb);

    dim3 grid(NTILES, SPLITS);   // 16 x 9 = 144 CTAs, one wave @ occ 1
    bpr_kernel<<<grid, 256, DSM_SIZE>>>(user_emb, item_emb, social, users, items, (float*)d_out);
}